// round 16
// baseline (speedup 1.0000x reference)
#include <cuda_runtime.h>
#include <cuda_fp16.h>
#include <math.h>
#include <stdint.h>

// PointLoss_like_GPS — GB300 sm_103a, Round 16
// Prep kernel converts all point sets to half2 SoA in GLOBAL memory once;
// scan kernel (persistent, R15 skeleton, R14 engine) reads ref groups via
// warp-uniform LDG.128 from L1 — no shared tiles, no conversion, no barriers
// in the hot path.

#define NPTS    4096
#define DIMS    3
#define THREADS 256
#define SPLITS  16
#define RSPLIT  (NPTS / SPLITS)      // 256 refs per item
#define QPT     2
#define QPB     (THREADS * QPT)      // 512 queries per item
#define MAXQ    32768
#define MAXSETS 8
#define FINB    32
#define GRID    608                  // 4 blocks/SM x 152 SMs, all co-resident

__device__ __align__(16) unsigned int g_hx[MAXSETS][NPTS / 2];  // half2 SoA
__device__ __align__(16) unsigned int g_hy[MAXSETS][NPTS / 2];
__device__ __align__(16) unsigned int g_hz[MAXSETS][NPTS / 2];
__device__ float        g_dmin[MAXQ * SPLITS];
__device__ float        g_fpart[FINB];
__device__ unsigned int g_work;
__device__ unsigned int g_ticket1;
__device__ unsigned int g_ticket2;

__device__ __forceinline__ __half2 h2_of(unsigned int u)
{
    return *reinterpret_cast<const __half2*>(&u);
}
__device__ __forceinline__ unsigned int u_of(__half2 h)
{
    return *reinterpret_cast<const unsigned int*>(&h);
}

// ---------------- prep: fp32 AoS -> half2 SoA global ------------------------
__global__ void __launch_bounds__(512)
prep_kernel(const float* __restrict__ a1, const float* __restrict__ a2)
{
    const int s   = blockIdx.x;            // set: even = a1[b], odd = a2[b]
    const int tid = threadIdx.x;
    const int bb  = s >> 1;
    const float* base = ((s & 1) ? a2 : a1) + (size_t)bb * NPTS * DIMS;

    for (int i = tid; i < NPTS / 2; i += 512) {
        const float* p = base + (size_t)i * 6;     // points 2i, 2i+1
        g_hx[s][i] = u_of(__floats2half2_rn(p[0], p[3]));
        g_hy[s][i] = u_of(__floats2half2_rn(p[1], p[4]));
        g_hz[s][i] = u_of(__floats2half2_rn(p[2], p[5]));
    }
}

// ---------------- scan: persistent work-stealing, LDG-broadcast refs --------
__global__ void __launch_bounds__(THREADS, 4)
gps_kernel(const float* __restrict__ a1,
           const float* __restrict__ a2,
           const float* __restrict__ alpha_p,
           const float* __restrict__ beta_p,
           float* __restrict__ out,
           int nq, int nitems, float scale)
{
    __shared__ float red[THREADS / 32];
    __shared__ unsigned int s_item;
    __shared__ unsigned int s_ticket;

    const int tid = threadIdx.x;

    for (;;) {
        __syncthreads();
        if (tid == 0) s_item = atomicAdd(&g_work, 1u);
        __syncthreads();
        const unsigned int it = s_item;
        if (it >= (unsigned)nitems) break;

        // item = pair*(8*SPLITS) + qc*SPLITS + sp
        const int sp   = it & (SPLITS - 1);
        const int qc   = (it >> 4) & 7;
        const int pair = it >> 7;
        const int b    = pair >> 1;

        const int qA = qc * QPB + tid;
        const int qB = qA + THREADS;

        const int sset = (pair & 1) ? (2 * b) : (2 * b + 1);   // samples set
        const int rset = sset ^ 1;                             // refs set

        // queries from the pre-converted half arrays (same rounding as before)
        const float* base1 = a1 + (size_t)b * NPTS * DIMS;
        const float* base2 = a2 + (size_t)b * NPTS * DIMS;
        const float* samples = (pair & 1) ? base1 : base2;

        const float qAx = samples[qA * 3 + 0];
        const float qAy = samples[qA * 3 + 1];
        const float qAz = samples[qA * 3 + 2];
        const float qBx = samples[qB * 3 + 0];
        const float qBy = samples[qB * 3 + 1];
        const float qBz = samples[qB * 3 + 2];

        const __half2 ax2 = __floats2half2_rn(qAx, qAx);
        const __half2 ay2 = __floats2half2_rn(qAy, qAy);
        const __half2 az2 = __floats2half2_rn(qAz, qAz);
        const __half2 bx2 = __floats2half2_rn(qBx, qBx);
        const __half2 by2 = __floats2half2_rn(qBy, qBy);
        const __half2 bz2 = __floats2half2_rn(qBz, qBz);

        const __half2 HMAXV = __float2half2_rn(65504.0f);
        __half2 am0 = HMAXV, am1 = HMAXV, am2 = HMAXV, am3 = HMAXV;
        __half2 bm0 = HMAXV, bm1 = HMAXV, bm2 = HMAXV, bm3 = HMAXV;

        // ref groups: warp-uniform LDG.128 (L1 broadcast), no smem
        const uint4* X = (const uint4*)g_hx[rset] + sp * (RSPLIT / 8);
        const uint4* Y = (const uint4*)g_hy[rset] + sp * (RSPLIT / 8);
        const uint4* Z = (const uint4*)g_hz[rset] + sp * (RSPLIT / 8);

        #pragma unroll 4
        for (int j = 0; j < RSPLIT / 8; j++) {
            const uint4 xv = __ldg(&X[j]);
            const uint4 yv = __ldg(&Y[j]);
            const uint4 zv = __ldg(&Z[j]);

            {   // query A
                const __half2 dx0 = __habs2(__hsub2(ax2, h2_of(xv.x)));
                const __half2 dy0 = __habs2(__hsub2(ay2, h2_of(yv.x)));
                const __half2 dz0 = __habs2(__hsub2(az2, h2_of(zv.x)));
                am0 = __hmin2(am0, __hadd2(__hadd2(dx0, dy0), dz0));

                const __half2 dx1 = __habs2(__hsub2(ax2, h2_of(xv.y)));
                const __half2 dy1 = __habs2(__hsub2(ay2, h2_of(yv.y)));
                const __half2 dz1 = __habs2(__hsub2(az2, h2_of(zv.y)));
                am1 = __hmin2(am1, __hadd2(__hadd2(dx1, dy1), dz1));

                const __half2 dx2 = __habs2(__hsub2(ax2, h2_of(xv.z)));
                const __half2 dy2 = __habs2(__hsub2(ay2, h2_of(yv.z)));
                const __half2 dz2 = __habs2(__hsub2(az2, h2_of(zv.z)));
                am2 = __hmin2(am2, __hadd2(__hadd2(dx2, dy2), dz2));

                const __half2 dx3 = __habs2(__hsub2(ax2, h2_of(xv.w)));
                const __half2 dy3 = __habs2(__hsub2(ay2, h2_of(yv.w)));
                const __half2 dz3 = __habs2(__hsub2(az2, h2_of(zv.w)));
                am3 = __hmin2(am3, __hadd2(__hadd2(dx3, dy3), dz3));
            }
            {   // query B
                const __half2 dx0 = __habs2(__hsub2(bx2, h2_of(xv.x)));
                const __half2 dy0 = __habs2(__hsub2(by2, h2_of(yv.x)));
                const __half2 dz0 = __habs2(__hsub2(bz2, h2_of(zv.x)));
                bm0 = __hmin2(bm0, __hadd2(__hadd2(dx0, dy0), dz0));

                const __half2 dx1 = __habs2(__hsub2(bx2, h2_of(xv.y)));
                const __half2 dy1 = __habs2(__hsub2(by2, h2_of(yv.y)));
                const __half2 dz1 = __habs2(__hsub2(bz2, h2_of(zv.y)));
                bm1 = __hmin2(bm1, __hadd2(__hadd2(dx1, dy1), dz1));

                const __half2 dx2 = __habs2(__hsub2(bx2, h2_of(xv.z)));
                const __half2 dy2 = __habs2(__hsub2(by2, h2_of(yv.z)));
                const __half2 dz2 = __habs2(__hsub2(bz2, h2_of(zv.z)));
                bm2 = __hmin2(bm2, __hadd2(__hadd2(dx2, dy2), dz2));

                const __half2 dx3 = __habs2(__hsub2(bx2, h2_of(xv.w)));
                const __half2 dy3 = __habs2(__hsub2(by2, h2_of(yv.w)));
                const __half2 dz3 = __habs2(__hsub2(bz2, h2_of(zv.w)));
                bm3 = __hmin2(bm3, __hadd2(__hadd2(dx3, dy3), dz3));
            }
        }

        const __half2 amv = __hmin2(__hmin2(am0, am1), __hmin2(am2, am3));
        const __half2 bmv = __hmin2(__hmin2(bm0, bm1), __hmin2(bm2, bm3));
        const float dminA = fminf(__low2float(amv), __high2float(amv));
        const float dminB = fminf(__low2float(bmv), __high2float(bmv));

        const size_t qrow = (size_t)(pair * NPTS);
        g_dmin[(qrow + qA) * SPLITS + sp] = dminA;
        g_dmin[(qrow + qB) * SPLITS + sp] = dminB;
    }

    // ---- block done: ticket; last FINB blocks finalize ----
    if (tid == 0) {
        __threadfence();
        s_ticket = atomicAdd(&g_ticket1, 1u);
    }
    __syncthreads();
    const unsigned int t = s_ticket;
    if (t < (unsigned)(GRID - FINB)) return;

    const int rank = (int)t - (GRID - FINB);

    if (tid == 0) {
        while (*((volatile unsigned int*)&g_ticket1) < (unsigned)GRID) { }
    }
    __syncthreads();
    __threadfence();

    const float alpha = *alpha_p;
    const float beta  = *beta_p;
    const float delta = __powf(alpha, -1.0f / beta);

    const int per_blk = nq / FINB;               // 1024 queries
    const int qbase   = rank * per_blk;
    const float4* dm4 = (const float4*)g_dmin;   // 4 float4 per query

    float acc = 0.0f;
    #pragma unroll 2
    for (int i = tid; i < per_blk; i += THREADS) {
        const size_t base = (size_t)(qbase + i) * 4;
        const float4 d0 = dm4[base + 0];
        const float4 d1 = dm4[base + 1];
        const float4 d2 = dm4[base + 2];
        const float4 d3 = dm4[base + 3];
        const float m0 = fminf(fminf(d0.x, d0.y), fminf(d0.z, d0.w));
        const float m1 = fminf(fminf(d1.x, d1.y), fminf(d1.z, d1.w));
        const float m2 = fminf(fminf(d2.x, d2.y), fminf(d2.z, d2.w));
        const float m3 = fminf(fminf(d3.x, d3.y), fminf(d3.z, d3.w));
        const float dmn = fminf(fminf(m0, m1), fminf(m2, m3));
        const float sv = alpha * __powf(dmn, beta) + delta;
        acc += -sv * __expf(-sv);
    }

    #pragma unroll
    for (int o = 16; o > 0; o >>= 1)
        acc += __shfl_down_sync(0xffffffffu, acc, o);
    if ((tid & 31) == 0) red[tid >> 5] = acc;
    __syncthreads();

    if (tid == 0) {
        float v = 0.0f;
        #pragma unroll
        for (int w = 0; w < THREADS / 32; w++) v += red[w];
        g_fpart[rank] = v;
        __threadfence();
        const unsigned int t2 = atomicAdd(&g_ticket2, 1u);
        if (t2 == FINB - 1) {
            float total = 0.0f;
            #pragma unroll
            for (int r = 0; r < FINB; r++)
                total += *((volatile float*)&g_fpart[r]);
            out[0] = total * scale;
            g_work    = 0;       // self-clean for graph replay
            g_ticket1 = 0;
            g_ticket2 = 0;
        }
    }
}

extern "C" void kernel_launch(void* const* d_in, const int* in_sizes, int n_in,
                              void* d_out, int out_size)
{
    const float* a1    = (const float*)d_in[0];
    const float* a2    = (const float*)d_in[1];
    const float* alpha = (const float*)d_in[2];
    const float* beta  = (const float*)d_in[3];
    float* out = (float*)d_out;

    const int B  = in_sizes[0] / (NPTS * DIMS);
    const int nq = 2 * B * NPTS;
    const int nitems = 2 * B * 8 * SPLITS;       // 1024 at B=4
    const float scale = 50.0f / (float)B;

    prep_kernel<<<2 * B, 512>>>(a1, a2);
    gps_kernel<<<GRID, THREADS>>>(a1, a2, alpha, beta, out, nq, nitems, scale);
}

// round 17
// speedup vs baseline: 1.3069x; 1.3069x over previous
#include <cuda_runtime.h>
#include <cuda_fp16.h>
#include <math.h>
#include <stdint.h>

// PointLoss_like_GPS — GB300 sm_103a, Round 17
// R14 skeleton/engine (best: 29.4us) with ROTATED coordinates:
//   u = x+y, v = x-y  =>  |dx|+|dy| = max(|du|,|dv|)   (exact identity)
// Inner loop per 2 refs: 3 HSUB2 + 1 HADD2 (fma) + HMNMX2-max + HMNMX2-min
// (alu) — fma-pipe ops per pair drop 5 -> 4 while we are measured at 84% of
// the fma SMSP cap. Rotation happens in tile conversion (one-time).

#define NPTS    4096
#define DIMS    3
#define THREADS 256
#define SPLITS  16
#define RSPLIT  (NPTS / SPLITS)      // 256 refs per block
#define QPT     2
#define QPB     (THREADS * QPT)      // 512 queries per block
#define MAXQ    32768
#define FINB    32

__device__ float        g_dmin[MAXQ * SPLITS];  // [q][split]
__device__ float        g_fpart[FINB];
__device__ unsigned int g_ticket1;
__device__ unsigned int g_ticket2;

__device__ __forceinline__ __half2 h2_of(unsigned int u)
{
    return *reinterpret_cast<const __half2*>(&u);
}

__global__ void __launch_bounds__(THREADS, 4)
gps_kernel(const float* __restrict__ a1,
           const float* __restrict__ a2,
           const float* __restrict__ alpha_p,
           const float* __restrict__ beta_p,
           float* __restrict__ out,
           int nq, int nblocks, float scale)
{
    __shared__ __align__(16) __half2 shU[RSPLIT / 2];   // x+y
    __shared__ __align__(16) __half2 shV[RSPLIT / 2];   // x-y
    __shared__ __align__(16) __half2 shZ[RSPLIT / 2];   // z
    __shared__ float red[THREADS / 32];
    __shared__ unsigned int s_ticket;

    const int tid = threadIdx.x;
    const int bx  = blockIdx.x;

    // bx = pair*(8*SPLITS) + qc*SPLITS + sp
    const int sp   = bx & (SPLITS - 1);
    const int qc   = (bx >> 4) & 7;
    const int pair = bx >> 7;
    const int b    = pair >> 1;

    const int qA = qc * QPB + tid;
    const int qB = qA + THREADS;

    const float* base1 = a1 + (size_t)b * NPTS * DIMS;
    const float* base2 = a2 + (size_t)b * NPTS * DIMS;
    const float* samples = (pair & 1) ? base1 : base2;
    const float* refs    = ((pair & 1) ? base2 : base1) + (size_t)sp * RSPLIT * DIMS;

    const float qAx = samples[qA * 3 + 0];
    const float qAy = samples[qA * 3 + 1];
    const float qAz = samples[qA * 3 + 2];
    const float qBx = samples[qB * 3 + 0];
    const float qBy = samples[qB * 3 + 1];
    const float qBz = samples[qB * 3 + 2];

    // rotated query coords
    const float qAu = qAx + qAy, qAv = qAx - qAy;
    const float qBu = qBx + qBy, qBv = qBx - qBy;

    const __half2 au2 = __floats2half2_rn(qAu, qAu);
    const __half2 av2 = __floats2half2_rn(qAv, qAv);
    const __half2 az2 = __floats2half2_rn(qAz, qAz);
    const __half2 bu2 = __floats2half2_rn(qBu, qBu);
    const __half2 bv2 = __floats2half2_rn(qBv, qBv);
    const __half2 bz2 = __floats2half2_rn(qBz, qBz);

    // tile: threads [0,128) convert + rotate 2 ref points each
    if (tid < RSPLIT / 2) {
        const float* p = refs + (size_t)tid * 6;
        const float u0 = p[0] + p[1], v0 = p[0] - p[1];
        const float u1 = p[3] + p[4], v1 = p[3] - p[4];
        shU[tid] = __floats2half2_rn(u0, u1);
        shV[tid] = __floats2half2_rn(v0, v1);
        shZ[tid] = __floats2half2_rn(p[2], p[5]);
    }
    __syncthreads();

    const __half2 HMAXV = __float2half2_rn(65504.0f);
    __half2 am0 = HMAXV, am1 = HMAXV, am2 = HMAXV, am3 = HMAXV;
    __half2 bm0 = HMAXV, bm1 = HMAXV, bm2 = HMAXV, bm3 = HMAXV;

    const uint4* U = (const uint4*)shU;   // 32 groups x 8 pts
    const uint4* V = (const uint4*)shV;
    const uint4* Z = (const uint4*)shZ;

    #pragma unroll 4
    for (int j = 0; j < RSPLIT / 8; j++) {
        const uint4 uv = U[j], vv = V[j], zv = Z[j];

        {   // query A: dist = max(|du|,|dv|) + |dz|
            const __half2 du0 = __hsub2(au2, h2_of(uv.x));
            const __half2 dv0 = __hsub2(av2, h2_of(vv.x));
            const __half2 dz0 = __hsub2(az2, h2_of(zv.x));
            const __half2 m0  = __hmax2(__habs2(du0), __habs2(dv0));
            am0 = __hmin2(am0, __hadd2(m0, __habs2(dz0)));

            const __half2 du1 = __hsub2(au2, h2_of(uv.y));
            const __half2 dv1 = __hsub2(av2, h2_of(vv.y));
            const __half2 dz1 = __hsub2(az2, h2_of(zv.y));
            const __half2 m1  = __hmax2(__habs2(du1), __habs2(dv1));
            am1 = __hmin2(am1, __hadd2(m1, __habs2(dz1)));

            const __half2 du2 = __hsub2(au2, h2_of(uv.z));
            const __half2 dv2 = __hsub2(av2, h2_of(vv.z));
            const __half2 dz2 = __hsub2(az2, h2_of(zv.z));
            const __half2 m2  = __hmax2(__habs2(du2), __habs2(dv2));
            am2 = __hmin2(am2, __hadd2(m2, __habs2(dz2)));

            const __half2 du3 = __hsub2(au2, h2_of(uv.w));
            const __half2 dv3 = __hsub2(av2, h2_of(vv.w));
            const __half2 dz3 = __hsub2(az2, h2_of(zv.w));
            const __half2 m3  = __hmax2(__habs2(du3), __habs2(dv3));
            am3 = __hmin2(am3, __hadd2(m3, __habs2(dz3)));
        }
        {   // query B
            const __half2 du0 = __hsub2(bu2, h2_of(uv.x));
            const __half2 dv0 = __hsub2(bv2, h2_of(vv.x));
            const __half2 dz0 = __hsub2(bz2, h2_of(zv.x));
            const __half2 m0  = __hmax2(__habs2(du0), __habs2(dv0));
            bm0 = __hmin2(bm0, __hadd2(m0, __habs2(dz0)));

            const __half2 du1 = __hsub2(bu2, h2_of(uv.y));
            const __half2 dv1 = __hsub2(bv2, h2_of(vv.y));
            const __half2 dz1 = __hsub2(bz2, h2_of(zv.y));
            const __half2 m1  = __hmax2(__habs2(du1), __habs2(dv1));
            bm1 = __hmin2(bm1, __hadd2(m1, __habs2(dz1)));

            const __half2 du2 = __hsub2(bu2, h2_of(uv.z));
            const __half2 dv2 = __hsub2(bv2, h2_of(vv.z));
            const __half2 dz2 = __hsub2(bz2, h2_of(zv.z));
            const __half2 m2  = __hmax2(__habs2(du2), __habs2(dv2));
            bm2 = __hmin2(bm2, __hadd2(m2, __habs2(dz2)));

            const __half2 du3 = __hsub2(bu2, h2_of(uv.w));
            const __half2 dv3 = __hsub2(bv2, h2_of(vv.w));
            const __half2 dz3 = __hsub2(bz2, h2_of(zv.w));
            const __half2 m3  = __hmax2(__habs2(du3), __habs2(dv3));
            bm3 = __hmin2(bm3, __hadd2(m3, __habs2(dz3)));
        }
    }

    const __half2 amv = __hmin2(__hmin2(am0, am1), __hmin2(am2, am3));
    const __half2 bmv = __hmin2(__hmin2(bm0, bm1), __hmin2(bm2, bm3));
    const float dminA = fminf(__low2float(amv), __high2float(amv));
    const float dminB = fminf(__low2float(bmv), __high2float(bmv));

    const size_t qrow = (size_t)(pair * NPTS);
    g_dmin[(qrow + qA) * SPLITS + sp] = dminA;
    g_dmin[(qrow + qB) * SPLITS + sp] = dminB;

    // ---- ticketed tail: last FINB blocks finalize (proven structure) ----
    __syncthreads();
    if (tid == 0) {
        __threadfence();
        s_ticket = atomicAdd(&g_ticket1, 1u);
    }
    __syncthreads();
    const unsigned int t = s_ticket;
    if (t < (unsigned)(nblocks - FINB)) return;

    const int rank = (int)t - (nblocks - FINB);

    if (tid == 0) {
        while (*((volatile unsigned int*)&g_ticket1) < (unsigned)nblocks) { }
    }
    __syncthreads();
    __threadfence();

    const float alpha = *alpha_p;
    const float beta  = *beta_p;
    const float delta = __powf(alpha, -1.0f / beta);

    const int per_blk = nq / FINB;               // 1024 queries
    const int qbase   = rank * per_blk;
    const float4* dm4 = (const float4*)g_dmin;   // 4 float4 per query

    float acc = 0.0f;
    #pragma unroll 2
    for (int i = tid; i < per_blk; i += THREADS) {
        const size_t base = (size_t)(qbase + i) * 4;
        const float4 d0 = dm4[base + 0];
        const float4 d1 = dm4[base + 1];
        const float4 d2 = dm4[base + 2];
        const float4 d3 = dm4[base + 3];
        const float m0 = fminf(fminf(d0.x, d0.y), fminf(d0.z, d0.w));
        const float m1 = fminf(fminf(d1.x, d1.y), fminf(d1.z, d1.w));
        const float m2 = fminf(fminf(d2.x, d2.y), fminf(d2.z, d2.w));
        const float m3 = fminf(fminf(d3.x, d3.y), fminf(d3.z, d3.w));
        const float dmn = fminf(fminf(m0, m1), fminf(m2, m3));
        const float sv = alpha * __powf(dmn, beta) + delta;
        acc += -sv * __expf(-sv);
    }

    #pragma unroll
    for (int o = 16; o > 0; o >>= 1)
        acc += __shfl_down_sync(0xffffffffu, acc, o);
    if ((tid & 31) == 0) red[tid >> 5] = acc;
    __syncthreads();

    if (tid == 0) {
        float v = 0.0f;
        #pragma unroll
        for (int w = 0; w < THREADS / 32; w++) v += red[w];
        g_fpart[rank] = v;
        __threadfence();
        const unsigned int t2 = atomicAdd(&g_ticket2, 1u);
        if (t2 == FINB - 1) {
            float total = 0.0f;
            #pragma unroll
            for (int r = 0; r < FINB; r++)
                total += *((volatile float*)&g_fpart[r]);
            out[0] = total * scale;
            g_ticket1 = 0;       // self-clean for graph replay
            g_ticket2 = 0;
        }
    }
}

extern "C" void kernel_launch(void* const* d_in, const int* in_sizes, int n_in,
                              void* d_out, int out_size)
{
    const float* a1    = (const float*)d_in[0];
    const float* a2    = (const float*)d_in[1];
    const float* alpha = (const float*)d_in[2];
    const float* beta  = (const float*)d_in[3];
    float* out = (float*)d_out;

    const int B  = in_sizes[0] / (NPTS * DIMS);
    const int nq = 2 * B * NPTS;
    const int nblocks = 2 * B * 8 * SPLITS;      // 1024 at B=4
    const float scale = 50.0f / (float)B;

    gps_kernel<<<nblocks, THREADS>>>(a1, a2, alpha, beta, out, nq, nblocks, scale);
}